// round 6
// baseline (speedup 1.0000x reference)
#include <cuda_runtime.h>
#include <math.h>

#define N1 6001
#define DD 64
#define LL 200
#define BB 32
#define PP 6400
#define MAXNZ 1024
#define RS 68   // k3 smem row stride in floats (272B, 16B-aligned, conflict-free)

// ---------------- device scratch (zero-initialized at load) ----------------
__device__ __align__(16) float g_h[N1*DD];
__device__ float g_wh1[N1];
__device__ float g_wh2[N1];
__device__ int   g_flags[N1];
__device__ __align__(16) float g_gat_i[N1*DD];
__device__ __align__(16) float g_trans_i[N1*DD];
__device__ __align__(16) float g_seqs_i[N1*DD];
__device__ __align__(16) float g_A1[N1*DD];
__device__ __align__(16) float g_A2[N1*DD];
__device__ __align__(16) float g_P1[LL*DD];
__device__ __align__(16) float g_P2[LL*DD];
__device__ __align__(16) float g_final[PP*DD];

__device__ __forceinline__ float mufu_rcp(float u){
    float r;
    asm("rcp.approx.f32 %0, %1;" : "=f"(r) : "f"(u));
    return r;
}
__device__ __forceinline__ void fma4(float4& a, float v, const float4& w){
    a.x=fmaf(v,w.x,a.x); a.y=fmaf(v,w.y,a.y); a.z=fmaf(v,w.z,a.z); a.w=fmaf(v,w.w,a.w);
}

// ============ K1 fused: hitem (bid<188, 32 rows) | pproj (188..194) | mark (195..219) ============
__global__ __launch_bounds__(256) void k1_fused(const float* __restrict__ emb,
        const float* __restrict__ Wi, const float* __restrict__ ai,
        const float* __restrict__ pe, const float* __restrict__ w1g,
        const float* __restrict__ w2g, const int* __restrict__ logs){
    __shared__ __align__(16) float Xs[2048];
    int t = threadIdx.x;
    int bid = blockIdx.x;
    if (bid >= 195){
        int p = (bid-195)*256 + t;
        g_flags[logs[p]] = 1;
        return;
    }
    if (bid < 188){
        int r0 = bid*32;
        for (int u=t; u<512; u+=256){
            int row=u>>4, col=u&15; int r=r0+row;
            float4 v = make_float4(0.f,0.f,0.f,0.f);
            if (r < N1) v = ((const float4*)emb)[r*16+col];
            ((float4*)Xs)[u] = v;
        }
        __syncthreads();
        int tp=t>>4, dq=t&15;
        float4 a0=make_float4(0.f,0.f,0.f,0.f), a1=a0;
        const float* x0=Xs+tp*64; const float* x1=Xs+(tp+16)*64;
        const float4* W4=(const float4*)Wi;
        #pragma unroll 8
        for (int k=0;k<64;k++){
            float4 w=__ldg(&W4[k*16+dq]);
            fma4(a0, x0[k], w);
            fma4(a1, x1[k], w);
        }
        int rA=r0+tp, rB=r0+tp+16;
        if (rA<N1) ((float4*)g_h)[rA*16+dq]=a0;
        if (rB<N1) ((float4*)g_h)[rB*16+dq]=a1;
        const float4* A4=(const float4*)ai;
        float4 v1=__ldg(&A4[dq]), v2=__ldg(&A4[16+dq]);
        float s1a=a0.x*v1.x+a0.y*v1.y+a0.z*v1.z+a0.w*v1.w;
        float s2a=a0.x*v2.x+a0.y*v2.y+a0.z*v2.z+a0.w*v2.w;
        float s1b=a1.x*v1.x+a1.y*v1.y+a1.z*v1.z+a1.w*v1.w;
        float s2b=a1.x*v2.x+a1.y*v2.y+a1.z*v2.z+a1.w*v2.w;
        #pragma unroll
        for (int o=8;o>0;o>>=1){
            s1a+=__shfl_xor_sync(0xffffffffu,s1a,o);
            s2a+=__shfl_xor_sync(0xffffffffu,s2a,o);
            s1b+=__shfl_xor_sync(0xffffffffu,s1b,o);
            s2b+=__shfl_xor_sync(0xffffffffu,s2b,o);
        }
        if (dq==0){
            if (rA<N1){ g_wh1[rA]=s1a; g_wh2[rA]=s2a; }
            if (rB<N1){ g_wh1[rB]=s1b; g_wh2[rB]=s2b; }
        }
        return;
    }
    // pproj
    {
        int l0=(bid-188)*32;
        for (int u=t; u<512; u+=256){
            int row=u>>4, col=u&15; int l=l0+row;
            float4 v = make_float4(0.f,0.f,0.f,0.f);
            if (l<LL) v = ((const float4*)pe)[l*16+col];
            ((float4*)Xs)[u]=v;
        }
        __syncthreads();
        int tp=t>>4, dq=t&15;
        float4 p1A=make_float4(0.f,0.f,0.f,0.f), p2A=p1A, p1B=p1A, p2B=p1A;
        const float* x0=Xs+tp*64; const float* x1=Xs+(tp+16)*64;
        const float4* W1=(const float4*)w1g; const float4* W2=(const float4*)w2g;
        #pragma unroll 8
        for (int k=0;k<64;k++){
            float4 w1=__ldg(&W1[k*16+dq]), w2=__ldg(&W2[k*16+dq]);
            float v0=x0[k], v1=x1[k];
            fma4(p1A,v0,w1); fma4(p2A,v0,w2);
            fma4(p1B,v1,w1); fma4(p2B,v1,w2);
        }
        int lA=l0+tp, lB=l0+tp+16;
        if (lA<LL){ ((float4*)g_P1)[lA*16+dq]=p1A; ((float4*)g_P2)[lA*16+dq]=p2A; }
        if (lB<LL){ ((float4*)g_P1)[lB*16+dq]=p1B; ((float4*)g_P2)[lB*16+dq]=p2B; }
    }
}

// ============ K2a: sparse GAT per UNIQUE item — one-pass MLP-8 scan, ballot compaction ============
__global__ __launch_bounds__(256) void k2a_gat(const float* __restrict__ adj){
    __shared__ int   s_idx[MAXNZ];
    __shared__ float s_val[MAXNZ];
    __shared__ float s_e[MAXNZ];
    __shared__ int   s_cnt;
    __shared__ float wred[8];
    __shared__ float pg[4][DD], pt[4][DD];
    int i = blockIdx.x;
    if (g_flags[i]==0) return;
    int t=threadIdx.x, lane=t&31, w=t>>5;
    if (t==0) s_cnt=0;
    __syncthreads();
    const float* row = adj + (size_t)i*(size_t)N1;
    unsigned lt_mask = (1u<<lane)-1u;
    // single pass: 3 batches x 8 front-batched coalesced loads per thread (MLP=8)
    #pragma unroll
    for (int base=0; base<6144; base+=2048){
        float vbuf[8];
        #pragma unroll
        for (int r2=0;r2<8;r2++){
            int j = base + r2*256 + t;
            vbuf[r2] = (j<N1)? __ldg(row+j) : 0.f;
        }
        unsigned msk[8]; int cnt[8]; int total=0;
        #pragma unroll
        for (int r2=0;r2<8;r2++){
            msk[r2]=__ballot_sync(0xffffffffu, vbuf[r2]>0.f);
            cnt[r2]=__popc(msk[r2]);
            total+=cnt[r2];
        }
        int wbase=0;
        if (lane==0 && total>0) wbase=atomicAdd(&s_cnt,total);
        wbase=__shfl_sync(0xffffffffu,wbase,0);
        int off=wbase;
        #pragma unroll
        for (int r2=0;r2<8;r2++){
            if (vbuf[r2]>0.f){
                int pos = off + __popc(msk[r2]&lt_mask);
                if (pos<MAXNZ){
                    s_idx[pos]=base + r2*256 + t;
                    s_val[pos]=vbuf[r2];
                }
            }
            off+=cnt[r2];
        }
    }
    __syncthreads();
    int n = s_cnt; if (n>MAXNZ) n=MAXNZ;
    int d=t&63, g4=t>>6;
    if (n==0){
        // exact fallback: softmax over all-(-9e15) row is uniform -> gat = mean(h)
        float s=0.f;
        for (int r=g4; r<N1; r+=4) s += g_h[r*DD+d];
        pg[g4][d]=s;
        __syncthreads();
        if (t<DD){
            float mm=(pg[0][t]+pg[1][t]+pg[2][t]+pg[3][t])*(1.f/(float)N1);
            g_gat_i[i*DD+t]=mm; g_trans_i[i*DD+t]=0.f;
        }
        if (t==0) g_flags[i]=0;
        return;
    }
    float wh1i = g_wh1[i];
    float m=-1e30f;
    for (int k=t;k<n;k+=256){
        float e = wh1i + g_wh2[s_idx[k]];
        e = (e>0.f)? e : 0.01f*e;
        s_e[k]=e;
        m = fmaxf(m,e);
    }
    #pragma unroll
    for (int o=16;o>0;o>>=1) m=fmaxf(m,__shfl_xor_sync(0xffffffffu,m,o));
    if (lane==0) wred[w]=m;
    __syncthreads();
    float M=wred[0];
    #pragma unroll
    for (int k=1;k<8;k++) M=fmaxf(M,wred[k]);
    __syncthreads();
    float ds=0.f;
    for (int k=t;k<n;k+=256){
        float wv=__expf(s_e[k]-M);
        s_e[k]=wv; ds+=wv;
    }
    #pragma unroll
    for (int o=16;o>0;o>>=1) ds += __shfl_xor_sync(0xffffffffu,ds,o);
    if (lane==0) wred[w]=ds;
    __syncthreads();
    float den=0.f;
    #pragma unroll
    for (int k=0;k<8;k++) den+=wred[k];
    float ga=0.f, ta=0.f;
    for (int k=g4;k<n;k+=4){
        float hv = g_h[s_idx[k]*DD+d];
        ga = fmaf(s_e[k],hv,ga);
        ta = fmaf(s_val[k],hv,ta);
    }
    pg[g4][d]=ga; pt[g4][d]=ta;
    __syncthreads();
    if (t<DD){
        float gg=(pg[0][t]+pg[1][t])+(pg[2][t]+pg[3][t]);
        float tt=(pt[0][t]+pt[1][t])+(pt[2][t]+pt[3][t]);
        float rden = mufu_rcp(den);
        g_gat_i[i*DD+t]=gg*rden; g_trans_i[i*DD+t]=tt;
    }
    if (t==0) g_flags[i]=0;
}

// ============ K2b_item: per-item coff/seqs + A1/A2 (256 thr, 32 rows, R=2, L1 weights) ============
__global__ __launch_bounds__(256) void k2b_item(const float* __restrict__ emb,
        const float* __restrict__ ccg, const float* __restrict__ cng,
        const float* __restrict__ w1g, const float* __restrict__ w2g){
    __shared__ __align__(16) float Xg[2048], Xt[2048], Xe[2048], X2[2048];
    int t=threadIdx.x;
    int r0=blockIdx.x*32;
    for (int u=t; u<512; u+=256){
        int row=u>>4, col=u&15; int r=r0+row;
        float4 g=make_float4(0.f,0.f,0.f,0.f), tv=g, e=g;
        if (r<N1){
            g =((float4*)g_gat_i)[r*16+col];
            tv=((float4*)g_trans_i)[r*16+col];
            e =((const float4*)emb)[r*16+col];
        }
        ((float4*)Xg)[u]=g; ((float4*)Xt)[u]=tv; ((float4*)Xe)[u]=e;
    }
    __syncthreads();
    int tp=t>>4, dq=t&15;
    float4 xA=make_float4(0.f,0.f,0.f,0.f), xB=xA;
    const float* g0=Xg+tp*64; const float* t0=Xt+tp*64;
    const float* g1=Xg+(tp+16)*64; const float* t1=Xt+(tp+16)*64;
    const float4* CC=(const float4*)ccg; const float4* CN=(const float4*)cng;
    #pragma unroll 8
    for (int k=0;k<64;k++){
        float4 c1=__ldg(&CC[k*16+dq]), c2=__ldg(&CN[k*16+dq]);
        fma4(xA,g0[k],c1); fma4(xA,t0[k],c2);
        fma4(xB,g1[k],c1); fma4(xB,t1[k],c2);
    }
    float4 cfA, cfB;
    cfA.x=mufu_rcp(1.f+__expf(-xA.x)); cfA.y=mufu_rcp(1.f+__expf(-xA.y));
    cfA.z=mufu_rcp(1.f+__expf(-xA.z)); cfA.w=mufu_rcp(1.f+__expf(-xA.w));
    cfB.x=mufu_rcp(1.f+__expf(-xB.x)); cfB.y=mufu_rcp(1.f+__expf(-xB.y));
    cfB.z=mufu_rcp(1.f+__expf(-xB.z)); cfB.w=mufu_rcp(1.f+__expf(-xB.w));
    float4 gA=((float4*)Xg)[tp*16+dq], tA4=((float4*)Xt)[tp*16+dq], eA=((float4*)Xe)[tp*16+dq];
    float4 gB=((float4*)Xg)[(tp+16)*16+dq], tB4=((float4*)Xt)[(tp+16)*16+dq], eB=((float4*)Xe)[(tp+16)*16+dq];
    float4 svA, svB;
    svA.x=cfA.x*gA.x+(1.f-cfA.x)*tA4.x+eA.x;
    svA.y=cfA.y*gA.y+(1.f-cfA.y)*tA4.y+eA.y;
    svA.z=cfA.z*gA.z+(1.f-cfA.z)*tA4.z+eA.z;
    svA.w=cfA.w*gA.w+(1.f-cfA.w)*tA4.w+eA.w;
    svB.x=cfB.x*gB.x+(1.f-cfB.x)*tB4.x+eB.x;
    svB.y=cfB.y*gB.y+(1.f-cfB.y)*tB4.y+eB.y;
    svB.z=cfB.z*gB.z+(1.f-cfB.z)*tB4.z+eB.z;
    svB.w=cfB.w*gB.w+(1.f-cfB.w)*tB4.w+eB.w;
    ((float4*)X2)[tp*16+dq]=svA;
    ((float4*)X2)[(tp+16)*16+dq]=svB;
    int rA=r0+tp, rB=r0+tp+16;
    if (rA<N1) ((float4*)g_seqs_i)[rA*16+dq]=svA;
    if (rB<N1) ((float4*)g_seqs_i)[rB*16+dq]=svB;
    __syncthreads();
    float4 a1A=make_float4(0.f,0.f,0.f,0.f), a2A=a1A, a1B=a1A, a2B=a1A;
    const float* xr0=X2+tp*64; const float* xr1=X2+(tp+16)*64;
    const float4* W1=(const float4*)w1g; const float4* W2=(const float4*)w2g;
    #pragma unroll 8
    for (int k=0;k<64;k++){
        float4 w1=__ldg(&W1[k*16+dq]), w2=__ldg(&W2[k*16+dq]);
        float v0=xr0[k], v1=xr1[k];
        fma4(a1A,v0,w1); fma4(a2A,v0,w2);
        fma4(a1B,v1,w1); fma4(a2B,v1,w2);
    }
    if (rA<N1){ ((float4*)g_A1)[rA*16+dq]=a1A; ((float4*)g_A2)[rA*16+dq]=a2A; }
    if (rB<N1){ ((float4*)g_A1)[rB*16+dq]=a1B; ((float4*)g_A2)[rB*16+dq]=a2B; }
}

// ============ K3: mirrored-pair causal attention, QT=8, 2 q-rows/thread ============
// grid (13, 32): pair p -> tiles (p, 24-p); p==12 self (tileB disabled).
__global__ __launch_bounds__(256,4) void k3_attn(const float* __restrict__ ba,
                                                 const int* __restrict__ logs){
    __shared__ __align__(16) float E1s[16*RS];
    __shared__ __align__(16) float E2c[32*RS];
    __shared__ __align__(16) float Sc[32*RS];
    __shared__ __align__(16) float bsS[64];
    __shared__ float scc[16*36];
    __shared__ int litem[32];
    int t=threadIdx.x, bb=blockIdx.y, p=blockIdx.x;
    bool hasB = (p!=12);
    int kendMax = 200 - 8*p;
    if (t<16) ((float4*)bsS)[t]=__ldg(((const float4*)ba)+t);
    // E1 staging: 16 rows (0-7 tileA, 8-15 tileB)
    {
        int r=t>>4, col=t&15;
        bool ok = (r<8) || hasB;
        if (ok){
            int q = (r<8)? (8*p+r) : (192-8*p + (r-8));
            int iq = logs[bb*LL+q];
            float m=(iq!=0)?1.f:0.f;
            float4 a=((const float4*)g_A1)[(size_t)iq*16+col];
            float4 pq=((const float4*)g_P1)[(size_t)q*16+col];
            float4 e;
            e.x=__expf(-fmaf(m,pq.x,a.x));
            e.y=__expf(-fmaf(m,pq.y,a.y));
            e.z=__expf(-fmaf(m,pq.z,a.z));
            e.w=__expf(-fmaf(m,pq.w,a.w));
            *(float4*)(E1s + r*RS + col*4) = e;
        }
    }
    __syncthreads();
    int w=t>>5, l=t&31;
    int qA = 8*p + w;
    int qB = 192 - 8*p + w;
    float2 aA=make_float2(0.f,0.f), aB=aA;
    for (int kbase=0; kbase<kendMax; kbase+=32){
        int rows = kendMax-kbase; if (rows>32) rows=32;
        if (t<rows) litem[t]=logs[bb*LL+kbase+t];
        __syncthreads();
        for (int u=t; u<rows*16; u+=256){
            int r=u>>4, col=u&15;
            int it=litem[r];
            int ll=kbase+r;
            float m=(it!=0)?1.f:0.f;
            float4 a=((const float4*)g_A2)[(size_t)it*16+col];
            float4 pq=((const float4*)g_P2)[(size_t)ll*16+col];
            float4 e;
            e.x=__expf(-fmaf(m,pq.x,a.x));
            e.y=__expf(-fmaf(m,pq.y,a.y));
            e.z=__expf(-fmaf(m,pq.z,a.z));
            e.w=__expf(-fmaf(m,pq.w,a.w));
            *(float4*)(E2c + r*RS + col*4) = e;
            *(float4*)(Sc  + r*RS + col*4) = ((const float4*)g_seqs_i)[(size_t)it*16+col];
        }
        __syncthreads();
        // ---- phase B: scores ----
        {
            bool doA = (kbase <= qA);
            bool doB = hasB;
            int kk=kbase+l;
            bool inA = doA && (l<rows) && (kk<=qA);
            bool inB = doB && (l<rows) && (kk<=qB);
            float accA=0.f, accB=0.f;
            const float4* e2p=(const float4*)(E2c + l*RS);
            const float4* bp=(const float4*)bsS;
            if (doA && doB){
                const float4* eAp=(const float4*)(E1s + w*RS);
                const float4* eBp=(const float4*)(E1s + (w+8)*RS);
                #pragma unroll
                for (int j=0;j<16;j++){
                    float4 e=e2p[j], b=bp[j], a=eAp[j], c=eBp[j];
                    accA=fmaf(b.x, mufu_rcp(fmaf(a.x,e.x,1.f)), accA);
                    accB=fmaf(b.x, mufu_rcp(fmaf(c.x,e.x,1.f)), accB);
                    accA=fmaf(b.y, mufu_rcp(fmaf(a.y,e.y,1.f)), accA);
                    accB=fmaf(b.y, mufu_rcp(fmaf(c.y,e.y,1.f)), accB);
                    accA=fmaf(b.z, mufu_rcp(fmaf(a.z,e.z,1.f)), accA);
                    accB=fmaf(b.z, mufu_rcp(fmaf(c.z,e.z,1.f)), accB);
                    accA=fmaf(b.w, mufu_rcp(fmaf(a.w,e.w,1.f)), accA);
                    accB=fmaf(b.w, mufu_rcp(fmaf(c.w,e.w,1.f)), accB);
                }
            } else if (doB){
                const float4* eBp=(const float4*)(E1s + (w+8)*RS);
                #pragma unroll
                for (int j=0;j<16;j++){
                    float4 e=e2p[j], b=bp[j], c=eBp[j];
                    accB=fmaf(b.x, mufu_rcp(fmaf(c.x,e.x,1.f)), accB);
                    accB=fmaf(b.y, mufu_rcp(fmaf(c.y,e.y,1.f)), accB);
                    accB=fmaf(b.z, mufu_rcp(fmaf(c.z,e.z,1.f)), accB);
                    accB=fmaf(b.w, mufu_rcp(fmaf(c.w,e.w,1.f)), accB);
                }
            } else if (doA){
                const float4* eAp=(const float4*)(E1s + w*RS);
                #pragma unroll
                for (int j=0;j<16;j++){
                    float4 e=e2p[j], b=bp[j], a=eAp[j];
                    accA=fmaf(b.x, mufu_rcp(fmaf(a.x,e.x,1.f)), accA);
                    accA=fmaf(b.y, mufu_rcp(fmaf(a.y,e.y,1.f)), accA);
                    accA=fmaf(b.z, mufu_rcp(fmaf(a.z,e.z,1.f)), accA);
                    accA=fmaf(b.w, mufu_rcp(fmaf(a.w,e.w,1.f)), accA);
                }
            }
            if (inA) scc[w*36+l]=accA;
            if (inB) scc[(w+8)*36+l]=accB;
        }
        __syncthreads();
        // ---- phase C: accumulate final (2 rows per thread, shared Sc read) ----
        {
            int klA = qA - kbase + 1; if (klA<0) klA=0; if (klA>rows) klA=rows;
            int klB = hasB? (qB - kbase + 1) : 0; if (klB>rows) klB=rows;
            const float* sA=scc + w*36;
            const float* sB=scc + (w+8)*36;
            int kl=0;
            for (; kl<klA; kl++){
                float2 s=*(const float2*)(Sc + kl*RS + l*2);
                float va=sA[kl], vb=sB[kl];
                aA.x=fmaf(va,s.x,aA.x); aA.y=fmaf(va,s.y,aA.y);
                aB.x=fmaf(vb,s.x,aB.x); aB.y=fmaf(vb,s.y,aB.y);
            }
            for (; kl<klB; kl++){
                float2 s=*(const float2*)(Sc + kl*RS + l*2);
                float vb=sB[kl];
                aB.x=fmaf(vb,s.x,aB.x); aB.y=fmaf(vb,s.y,aB.y);
            }
        }
        __syncthreads();
    }
    *(float2*)(g_final + (size_t)(bb*LL+qA)*64 + l*2) = aA;
    if (hasB) *(float2*)(g_final + (size_t)(bb*LL+qB)*64 + l*2) = aB;
}

// ============ K4: FFN + UpDown + logits (256 thr, 32 rows, L1 weights) ============
__global__ __launch_bounds__(256,4) void k4_ffn(const int* __restrict__ poss,
        const int* __restrict__ negs, const float* __restrict__ emb,
        const float* __restrict__ c1wg,const float* __restrict__ c1bg,
        const float* __restrict__ c2wg,const float* __restrict__ c2bg,
        const float* __restrict__ uwg,const float* __restrict__ ubg,
        const float* __restrict__ gwg,const float* __restrict__ gbg,
        const float* __restrict__ dwg,const float* __restrict__ dbg,
        float* __restrict__ out){
    __shared__ __align__(16) float fin[2048], f1[2048], fin2[2048], hb[4096], fin3[2048];
    int t=threadIdx.x;
    int p0=blockIdx.x*32;
    for (int u=t; u<512; u+=256)
        ((float4*)fin)[u]=((float4*)g_final)[(size_t)p0*16+u];
    __syncthreads();
    int tp=t>>4, dq=t&15;
    // stage 1: f1 = relu(fin@c1w + c1b)
    {
        float4 b=__ldg(((const float4*)c1bg)+dq);
        float4 a0=b, a1=b;
        const float* x0=fin+tp*64; const float* x1=fin+(tp+16)*64;
        const float4* W=(const float4*)c1wg;
        #pragma unroll 8
        for (int k=0;k<64;k++){
            float4 w=__ldg(&W[k*16+dq]);
            fma4(a0,x0[k],w); fma4(a1,x1[k],w);
        }
        a0.x=fmaxf(a0.x,0.f); a0.y=fmaxf(a0.y,0.f); a0.z=fmaxf(a0.z,0.f); a0.w=fmaxf(a0.w,0.f);
        a1.x=fmaxf(a1.x,0.f); a1.y=fmaxf(a1.y,0.f); a1.z=fmaxf(a1.z,0.f); a1.w=fmaxf(a1.w,0.f);
        ((float4*)f1)[tp*16+dq]=a0;
        ((float4*)f1)[(tp+16)*16+dq]=a1;
    }
    __syncthreads();
    // stage 2: fin2 = fin + f1@c2w + c2b
    {
        float4 b=__ldg(((const float4*)c2bg)+dq);
        float4 a0=b, a1=b;
        const float* x0=f1+tp*64; const float* x1=f1+(tp+16)*64;
        const float4* W=(const float4*)c2wg;
        #pragma unroll 8
        for (int k=0;k<64;k++){
            float4 w=__ldg(&W[k*16+dq]);
            fma4(a0,x0[k],w); fma4(a1,x1[k],w);
        }
        float4 fA=((float4*)fin)[tp*16+dq], fB=((float4*)fin)[(tp+16)*16+dq];
        a0.x+=fA.x; a0.y+=fA.y; a0.z+=fA.z; a0.w+=fA.w;
        a1.x+=fB.x; a1.y+=fB.y; a1.z+=fB.z; a1.w+=fB.w;
        ((float4*)fin2)[tp*16+dq]=a0;
        ((float4*)fin2)[(tp+16)*16+dq]=a1;
    }
    __syncthreads();
    // stage 3: hb = relu(fin2@gw+gb) * (fin2@uw+ub); 32 f4-cols x 8 row-groups, R=4
    {
        int rp=t>>5, dz=t&31;
        float4 ub4=__ldg(((const float4*)ubg)+dz);
        float4 gb4=__ldg(((const float4*)gbg)+dz);
        float4 aU[4], aG[4];
        #pragma unroll
        for (int j=0;j<4;j++){ aU[j]=ub4; aG[j]=gb4; }
        const float4* U=(const float4*)uwg; const float4* G=(const float4*)gwg;
        #pragma unroll 4
        for (int k=0;k<64;k++){
            float4 wu=__ldg(&U[k*32+dz]), wg=__ldg(&G[k*32+dz]);
            #pragma unroll
            for (int j=0;j<4;j++){
                float xv=fin2[(rp+8*j)*64+k];
                fma4(aU[j],xv,wu); fma4(aG[j],xv,wg);
            }
        }
        #pragma unroll
        for (int j=0;j<4;j++){
            float4 h;
            h.x=fmaxf(aG[j].x,0.f)*aU[j].x; h.y=fmaxf(aG[j].y,0.f)*aU[j].y;
            h.z=fmaxf(aG[j].z,0.f)*aU[j].z; h.w=fmaxf(aG[j].w,0.f)*aU[j].w;
            ((float4*)hb)[(rp+8*j)*32+dz]=h;
        }
    }
    __syncthreads();
    // stage 4: fin3 = fin2 + relu(hb@dw + db)
    {
        float4 b=__ldg(((const float4*)dbg)+dq);
        float4 a0=b, a1=b;
        const float* h0=hb+tp*128; const float* h1=hb+(tp+16)*128;
        const float4* W=(const float4*)dwg;
        #pragma unroll 8
        for (int k=0;k<128;k++){
            float4 w=__ldg(&W[k*16+dq]);
            fma4(a0,h0[k],w); fma4(a1,h1[k],w);
        }
        float4 fA=((float4*)fin2)[tp*16+dq], fB=((float4*)fin2)[(tp+16)*16+dq];
        float4 o0, o1;
        o0.x=fA.x+fmaxf(a0.x,0.f); o0.y=fA.y+fmaxf(a0.y,0.f);
        o0.z=fA.z+fmaxf(a0.z,0.f); o0.w=fA.w+fmaxf(a0.w,0.f);
        o1.x=fB.x+fmaxf(a1.x,0.f); o1.y=fB.y+fmaxf(a1.y,0.f);
        o1.z=fB.z+fmaxf(a1.z,0.f); o1.w=fB.w+fmaxf(a1.w,0.f);
        ((float4*)fin3)[tp*16+dq]=o0;
        ((float4*)fin3)[(tp+16)*16+dq]=o1;
    }
    __syncthreads();
    // logits: 8 warps x 8 tasks = 32 rows x {pos,neg}
    {
        int w=t>>5, lane=t&31;
        #pragma unroll
        for (int it=0; it<8; it++){
            int task=w*8+it;
            int which=task&1, row=task>>1;
            int pidx=p0+row;
            int idx = which? negs[pidx] : poss[pidx];
            const float* er=emb+(size_t)idx*64;
            const float* fr=fin3+row*64;
            float s=fr[lane]*er[lane]+fr[lane+32]*er[lane+32];
            #pragma unroll
            for (int o=16;o>0;o>>=1) s+=__shfl_xor_sync(0xffffffffu,s,o);
            if (lane==0) out[which*PP+pidx]=s;
        }
    }
}

// ---------------- host launcher ----------------
extern "C" void kernel_launch(void* const* d_in, const int* in_sizes, int n_in,
                              void* d_out, int out_size){
    const int*   logs = (const int*)  d_in[0];
    const int*   poss = (const int*)  d_in[1];
    const int*   negs = (const int*)  d_in[2];
    const float* adj  = (const float*)d_in[4];
    const float* emb  = (const float*)d_in[5];
    const float* pe   = (const float*)d_in[6];
    const float* Wi   = (const float*)d_in[7];
    const float* ai   = (const float*)d_in[8];
    const float* W1   = (const float*)d_in[9];
    const float* W2   = (const float*)d_in[10];
    const float* ba   = (const float*)d_in[11];
    const float* ccg  = (const float*)d_in[12];
    const float* cng  = (const float*)d_in[13];
    const float* c1w  = (const float*)d_in[14];
    const float* c1b  = (const float*)d_in[15];
    const float* c2w  = (const float*)d_in[16];
    const float* c2b  = (const float*)d_in[17];
    const float* uw   = (const float*)d_in[18];
    const float* ub   = (const float*)d_in[19];
    const float* gw   = (const float*)d_in[20];
    const float* gb   = (const float*)d_in[21];
    const float* dw   = (const float*)d_in[22];
    const float* db   = (const float*)d_in[23];
    float* out = (float*)d_out;

    k1_fused<<<220,256>>>(emb, Wi, ai, pe, W1, W2, logs);
    k2a_gat<<<N1,256>>>(adj);
    k2b_item<<<188,256>>>(emb, ccg, cng, W1, W2);
    dim3 g3(13, BB);
    k3_attn<<<g3,256>>>(ba, logs);
    k4_ffn<<<200,256>>>(poss, negs, emb, c1w,c1b,c2w,c2b, uw,ub,gw,gb, dw,db, out);
}